// round 2
// baseline (speedup 1.0000x reference)
#include <cuda_runtime.h>
#include <cuda_bf16.h>
#include <cstdint>

#define N_SEGMENTS 50000
#define N_FEAT4    16          // float4 per row (64 floats)
#define CAP        128         // bucket capacity per segment (Poisson(32): P(>128) ~ 1e-30)
#define OVF_MAX    (1 << 20)   // overflow list capacity (safety net)

// ---------------------------------------------------------------------------
// Static device scratch (no allocations allowed).
// ---------------------------------------------------------------------------
__device__ int g_cnt[N_SEGMENTS];            // per-segment row count
__device__ int g_bucket[N_SEGMENTS * CAP];   // row ids per segment (25.6 MB)
__device__ int g_ovf_n;                      // overflow entries
__device__ int g_ovf[OVF_MAX];               // overflow row ids

__device__ __forceinline__ float4 add4(float4 a, float4 b) {
    return make_float4(a.x + b.x, a.y + b.y, a.z + b.z, a.w + b.w);
}

// Inline int64-vs-int32 detection: if the index buffer is int64 with values
// < 50000, every odd 32-bit word is zero. 8 samples -> false-positive
// probability with int32 data ~ (1/50000)^8 ~ 2.6e-38. Uniform broadcast
// loads, L1-hit after first warp.
__device__ __forceinline__ bool idx_is64(const void* idx_raw) {
    const unsigned int* w = (const unsigned int*)idx_raw;
    unsigned int acc = w[1] | w[3] | w[5] | w[7] | w[9] | w[11] | w[13] | w[15];
    return acc == 0u;
}

__device__ __forceinline__ int load_seg(const void* idx_raw, bool is64, int row) {
    if (is64) return (int)((const long long*)idx_raw)[row];
    return ((const int*)idx_raw)[row];
}

// ---------------------------------------------------------------------------
// Kernel 1: zero counters + overflow count.
// ---------------------------------------------------------------------------
__global__ void zero_cnt_kernel() {
    int i = blockIdx.x * blockDim.x + threadIdx.x;
    if (i < N_SEGMENTS) g_cnt[i] = 0;
    if (i == 0) g_ovf_n = 0;
}

// ---------------------------------------------------------------------------
// Kernel 2: scatter row ids into per-segment buckets.
// 1 thread per row: atomicAdd on the segment counter, then a 4-byte store.
// ---------------------------------------------------------------------------
__global__ void __launch_bounds__(256)
scatter_idx_kernel(const void* __restrict__ idx_raw, int n_rows) {
    const bool is64 = idx_is64(idx_raw);
    int r = blockIdx.x * blockDim.x + threadIdx.x;
    if (r >= n_rows) return;

    int seg = load_seg(idx_raw, is64, r);
    int slot = atomicAdd(&g_cnt[seg], 1);
    if (slot < CAP) {
        g_bucket[seg * CAP + slot] = r;
    } else {
        int o = atomicAdd(&g_ovf_n, 1);
        if (o < OVF_MAX) g_ovf[o] = r;
    }
}

// ---------------------------------------------------------------------------
// Kernel 3: gather-sum. 16 lanes per segment; lane owns one float4 column.
// Bucket row-id loads are uniform within the 16-lane group (broadcast).
// 4 accumulators for MLP on the random 256B row reads. Plain store at end
// (also clears the 0xAA poison for empty segments).
// ---------------------------------------------------------------------------
__global__ void __launch_bounds__(256)
gather_kernel(const float4* __restrict__ in, float4* __restrict__ out) {
    int g    = blockIdx.x * 16 + (threadIdx.x >> 4);   // segment id
    int lane = threadIdx.x & 15;                       // float4 column
    if (g >= N_SEGMENTS) return;

    int n = g_cnt[g];
    if (n > CAP) n = CAP;

    const int* bk = &g_bucket[g * CAP];
    float4 a0 = make_float4(0.f, 0.f, 0.f, 0.f);
    float4 a1 = a0, a2 = a0, a3 = a0;

    int i = 0;
    for (; i + 4 <= n; i += 4) {
        int4 rr = *(const int4*)(bk + i);   // 16B-aligned (CAP*4 = 512B rows)
        a0 = add4(a0, __ldg(&in[rr.x * N_FEAT4 + lane]));
        a1 = add4(a1, __ldg(&in[rr.y * N_FEAT4 + lane]));
        a2 = add4(a2, __ldg(&in[rr.z * N_FEAT4 + lane]));
        a3 = add4(a3, __ldg(&in[rr.w * N_FEAT4 + lane]));
    }
    for (; i < n; ++i) {
        a0 = add4(a0, __ldg(&in[bk[i] * N_FEAT4 + lane]));
    }

    float4 s = add4(add4(a0, a1), add4(a2, a3));
    out[g * N_FEAT4 + lane] = s;
}

// ---------------------------------------------------------------------------
// Kernel 4: overflow fixup (normally 0 entries). red.v4 adds on top of the
// gather stores.
// ---------------------------------------------------------------------------
__global__ void __launch_bounds__(256)
overflow_kernel(const float4* __restrict__ in, const void* __restrict__ idx_raw,
                float* __restrict__ out) {
    int cnt = g_ovf_n;
    if (cnt <= 0) return;
    if (cnt > OVF_MAX) cnt = OVF_MAX;

    const bool is64 = idx_is64(idx_raw);
    int t    = blockIdx.x * blockDim.x + threadIdx.x;
    int lane = t & 15;
    int e    = t >> 4;
    int estr = (gridDim.x * blockDim.x) >> 4;

    for (; e < cnt; e += estr) {
        int r   = g_ovf[e];
        int seg = load_seg(idx_raw, is64, r);
        float4 v = in[r * N_FEAT4 + lane];
        float* dst = out + (long long)seg * 64 + lane * 4;
        asm volatile(
            "red.global.add.v4.f32 [%0], {%1, %2, %3, %4};"
            :: "l"(dst), "f"(v.x), "f"(v.y), "f"(v.z), "f"(v.w)
            : "memory");
    }
}

// ---------------------------------------------------------------------------
// Launch
// ---------------------------------------------------------------------------
extern "C" void kernel_launch(void* const* d_in, const int* in_sizes, int n_in,
                              void* d_out, int out_size) {
    const float4* in  = (const float4*)d_in[0];
    const void*   idx = (const void*)d_in[1];
    float4*       out = (float4*)d_out;

    // Row count from the input tensor (robust to idx dtype/size reporting).
    const int n_rows = in_sizes[0] / 64;

    zero_cnt_kernel<<<(N_SEGMENTS + 255) / 256, 256>>>();

    scatter_idx_kernel<<<(n_rows + 255) / 256, 256>>>(idx, n_rows);

    gather_kernel<<<(N_SEGMENTS + 15) / 16, 256>>>(in, out);

    overflow_kernel<<<32, 256>>>(in, idx, (float*)d_out);
}

// round 3
// speedup vs baseline: 1.2055x; 1.2055x over previous
#include <cuda_runtime.h>
#include <cuda_bf16.h>
#include <cstdint>

#define N_SEGMENTS 50000
#define N_FEAT4    16          // float4 per row (64 floats)

// ---------------------------------------------------------------------------
// Inline int64-vs-int32 detection: if the index buffer is int64 with values
// < 50000, every odd 32-bit word is the zero high half. 8 samples ->
// false-positive probability with int32 data ~ (1/50000)^8 ~ 2.6e-38.
// Same-address broadcast loads, L1-hit after the first warp.
// ---------------------------------------------------------------------------
__device__ __forceinline__ bool idx_is64(const void* idx_raw) {
    const unsigned int* w = (const unsigned int*)idx_raw;
    unsigned int acc = w[1] | w[3] | w[5] | w[7] | w[9] | w[11] | w[13] | w[15];
    return acc == 0u;
}

// ---------------------------------------------------------------------------
// Kernel 1: zero the output (harness poisons it with 0xAA).
// ---------------------------------------------------------------------------
__global__ void zero_out_kernel(float4* __restrict__ out, int n_vec4) {
    int i = blockIdx.x * blockDim.x + threadIdx.x;
    if (i < n_vec4) out[i] = make_float4(0.f, 0.f, 0.f, 0.f);
}

// ---------------------------------------------------------------------------
// Kernel 2: scatter-add. Persistent grid-stride; each 16-lane group handles
// 4 consecutive rows per iteration. Per lane/iter: 4 idx loads (1-2 sectors
// per warp, consecutive rows) + 4 LDG.128 (fully coalesced 256B/row) batched
// for MLP=8, then 4 red.global.add.v4.f32 (no return -> no scoreboard wait).
// ---------------------------------------------------------------------------
__global__ void __launch_bounds__(256)
aggr_kernel(const float4* __restrict__ in,
            const void* __restrict__ idx_raw,
            float* __restrict__ out,
            int n_rows) {
    const bool is64 = idx_is64(idx_raw);
    const int* __restrict__ iw = (const int*)idx_raw;   // low words when int64
    const int istep = is64 ? 2 : 1;

    const int group   = (blockIdx.x * blockDim.x + threadIdx.x) >> 4;
    const int lane    = threadIdx.x & 15;
    const int ngroups = (gridDim.x * blockDim.x) >> 4;

    for (int base = group * 4; base < n_rows; base += ngroups * 4) {
        const int r0 = base, r1 = base + 1, r2 = base + 2, r3 = base + 3;
        const bool p1 = r1 < n_rows, p2 = r2 < n_rows, p3 = r3 < n_rows;

        // Batched index loads (consecutive rows -> adjacent words).
        int s0 = iw[r0 * istep];
        int s1 = p1 ? iw[r1 * istep] : 0;
        int s2 = p2 ? iw[r2 * istep] : 0;
        int s3 = p3 ? iw[r3 * istep] : 0;

        // Batched row loads (MLP=4 per lane; 256B contiguous per row).
        float4 v0 = __ldg(&in[r0 * N_FEAT4 + lane]);
        float4 v1 = p1 ? __ldg(&in[r1 * N_FEAT4 + lane]) : make_float4(0, 0, 0, 0);
        float4 v2 = p2 ? __ldg(&in[r2 * N_FEAT4 + lane]) : make_float4(0, 0, 0, 0);
        float4 v3 = p3 ? __ldg(&in[r3 * N_FEAT4 + lane]) : make_float4(0, 0, 0, 0);

        float* d0 = out + s0 * 64 + lane * 4;
        asm volatile("red.global.add.v4.f32 [%0], {%1, %2, %3, %4};"
                     :: "l"(d0), "f"(v0.x), "f"(v0.y), "f"(v0.z), "f"(v0.w) : "memory");
        if (p1) {
            float* d1 = out + s1 * 64 + lane * 4;
            asm volatile("red.global.add.v4.f32 [%0], {%1, %2, %3, %4};"
                         :: "l"(d1), "f"(v1.x), "f"(v1.y), "f"(v1.z), "f"(v1.w) : "memory");
        }
        if (p2) {
            float* d2 = out + s2 * 64 + lane * 4;
            asm volatile("red.global.add.v4.f32 [%0], {%1, %2, %3, %4};"
                         :: "l"(d2), "f"(v2.x), "f"(v2.y), "f"(v2.z), "f"(v2.w) : "memory");
        }
        if (p3) {
            float* d3 = out + s3 * 64 + lane * 4;
            asm volatile("red.global.add.v4.f32 [%0], {%1, %2, %3, %4};"
                         :: "l"(d3), "f"(v3.x), "f"(v3.y), "f"(v3.z), "f"(v3.w) : "memory");
        }
    }
}

// ---------------------------------------------------------------------------
// Launch
// ---------------------------------------------------------------------------
extern "C" void kernel_launch(void* const* d_in, const int* in_sizes, int n_in,
                              void* d_out, int out_size) {
    const float4* in  = (const float4*)d_in[0];
    const void*   idx = (const void*)d_in[1];
    float*        out = (float*)d_out;

    const int n_rows = in_sizes[0] / 64;    // 1,600,000

    const int n_vec4 = out_size / 4;        // 3.2M floats -> 800K float4
    zero_out_kernel<<<(n_vec4 + 255) / 256, 256>>>((float4*)d_out, n_vec4);

    // Persistent-ish grid: 148 SMs x 16 blocks, 16 groups/block.
    const int blocks = 2368;
    aggr_kernel<<<blocks, 256>>>(in, idx, out, n_rows);
}